// round 2
// baseline (speedup 1.0000x reference)
#include <cuda_runtime.h>
#include <math.h>

#define B_ 16
#define C_ 64
#define HW_ 2304
#define EPSS 1e-8f
#define NORM_EPS 1e-12f
#define INV_HW (1.0f/2304.0f)
#define MSIZE ((size_t)B_*(size_t)HW_*(size_t)HW_)

// ---------------- scratch (device globals; no runtime allocation) ----------
__device__ float g_Xn[B_][C_][HW_];   // normalized X, [c][i] layout (coalesced everywhere)
__device__ float g_Yn[B_][C_][HW_];
__device__ float g_u[B_][HW_];
__device__ float g_v[B_][HW_];
__device__ float g_w[4][B_][C_];      // w0 = Yn@c ; w1 = Xn@u1 ; w2 = Yn@v1 ; w3 = Xn@u2
__device__ float g_S[B_][4];          // S_u1, S_v1, S_u2
__device__ float g_sim[B_];

// ---------------- init: zero the accumulators (runs first every replay) ----
__global__ void init_kernel() {
    int tid = threadIdx.x;
    float* w = &g_w[0][0][0];
    for (int i = tid; i < 4*B_*C_; i += blockDim.x) w[i] = 0.f;
    if (tid < B_*4) (&g_S[0][0])[tid] = 0.f;
    if (tid < B_)   g_sim[tid] = 0.f;
}

// ---------------- normalize along C; Y also accumulates w0 = Yn @ c --------
template<bool IS_Y>
__global__ void norm_kernel(const float* __restrict__ src) {
    __shared__ float s[C_][129];   // padded: conflict-free column reads
    __shared__ float invn[128];
    __shared__ float wacc[C_];
    int b  = blockIdx.y;
    int i0 = blockIdx.x * 128;
    int tid = threadIdx.x;
    if (IS_Y && tid < C_) wacc[tid] = 0.f;

    const float* sp = src + (size_t)b * C_ * HW_ + i0;
    for (int idx = tid; idx < C_*128; idx += 256) {
        int c = idx >> 7, ii = idx & 127;
        s[c][ii] = sp[(size_t)c * HW_ + ii];
    }
    __syncthreads();
    if (tid < 128) {
        float ss = 0.f;
        #pragma unroll
        for (int c = 0; c < C_; c++) { float v = s[c][tid]; ss = fmaf(v, v, ss); }
        float n = sqrtf(ss);
        invn[tid] = 1.0f / fmaxf(n, NORM_EPS);
    }
    __syncthreads();

    float (*dst)[HW_] = IS_Y ? g_Yn[b] : g_Xn[b];
    for (int idx = tid; idx < C_*128; idx += 256) {
        int c = idx >> 7, ii = idx & 127;
        float v = s[c][ii] * invn[ii];
        dst[c][i0 + ii] = v;
        if (IS_Y) {
            // warp spans 32 consecutive ii at fixed c -> reduce then smem atomic
            #pragma unroll
            for (int off = 16; off > 0; off >>= 1)
                v += __shfl_down_sync(0xffffffffu, v, off);
            if ((tid & 31) == 0) atomicAdd(&wacc[c], v);
        }
    }
    if (IS_Y) {
        __syncthreads();
        if (tid < C_) atomicAdd(&g_w[0][b][tid], wacc[tid] * INV_HW);
    }
}

// ---------------- one Sinkhorn half-step (rank-structured matvec) ----------
// stage 0: u1 = 1/(S_c - x.w0 + eps)        ; w1 = Xn@u1, S_u1
// stage 1: v1 = 1/(S_u1 - y.w1 + eps)       ; w2 = Yn@v1, S_v1
// stage 2: u2 = r/(S_v1 - x.w2 + eps)       ; w3 = Xn@u2, S_u2
// stage 3: v2 = c/(S_u2 - y.w3 + eps)       ; (final)
__global__ void pass_kernel(int stage) {
    __shared__ float ws[C_];
    __shared__ float us[256];
    int b   = blockIdx.y;
    int i0  = blockIdx.x * 256;
    int tid = threadIdx.x;

    const float (*Mat)[HW_]; const float* win;
    float numer, Sval; float* uout; float* wout; float* Sout;
    if (stage == 0)      { Mat = g_Xn[b]; win = g_w[0][b]; numer = 1.f;    Sval = (float)HW_ * INV_HW; uout = g_u[b]; wout = g_w[1][b]; Sout = &g_S[b][0]; }
    else if (stage == 1) { Mat = g_Yn[b]; win = g_w[1][b]; numer = 1.f;    Sval = g_S[b][0];           uout = g_v[b]; wout = g_w[2][b]; Sout = &g_S[b][1]; }
    else if (stage == 2) { Mat = g_Xn[b]; win = g_w[2][b]; numer = INV_HW; Sval = g_S[b][1];           uout = g_u[b]; wout = g_w[3][b]; Sout = &g_S[b][2]; }
    else                 { Mat = g_Yn[b]; win = g_w[3][b]; numer = INV_HW; Sval = g_S[b][2];           uout = g_v[b]; wout = nullptr;   Sout = nullptr;    }

    if (tid < C_) ws[tid] = win[tid];
    __syncthreads();

    int i = i0 + tid;
    float dot = 0.f;
    #pragma unroll 16
    for (int c = 0; c < C_; c++) dot = fmaf(Mat[c][i], ws[c], dot);
    float u = numer / (Sval - dot + EPSS);
    uout[i] = u;
    us[tid] = u;
    __syncthreads();

    if (wout) {
        int warp = tid >> 5, lane = tid & 31;
        #pragma unroll
        for (int c8 = 0; c8 < 8; c8++) {
            int c = warp * 8 + c8;
            float p = 0.f;
            #pragma unroll
            for (int t = 0; t < 8; t++)
                p = fmaf(Mat[c][i0 + lane + t*32], us[lane + t*32], p);
            #pragma unroll
            for (int off = 16; off > 0; off >>= 1)
                p += __shfl_down_sync(0xffffffffu, p, off);
            if (lane == 0) atomicAdd(&wout[c], p);
        }
        float sv = us[tid];
        #pragma unroll
        for (int off = 16; off > 0; off >>= 1)
            sv += __shfl_down_sync(0xffffffffu, sv, off);
        if (lane == 0) atomicAdd(Sout, sv);
    }
}

// ---------------- big kernel: M tile (128x128, K=64) + similarity ----------
__global__ void __launch_bounds__(256, 2) gemm_kernel(float* __restrict__ outM) {
    __shared__ float As[32][128];
    __shared__ float Bs[32][128];
    __shared__ float us[128], vs[128];
    __shared__ float red[8];
    int b  = blockIdx.z;
    int i0 = blockIdx.y * 128;
    int j0 = blockIdx.x * 128;
    int tid = threadIdx.x;
    int ty = tid >> 4, tx = tid & 15;

    if (tid < 128) { us[tid] = g_u[b][i0 + tid]; vs[tid] = g_v[b][j0 + tid]; }

    float acc[8][8];
    #pragma unroll
    for (int r = 0; r < 8; r++)
        #pragma unroll
        for (int q = 0; q < 8; q++) acc[r][q] = 0.f;

    for (int k0 = 0; k0 < C_; k0 += 32) {
        __syncthreads();
        #pragma unroll
        for (int t = 0; t < 16; t++) {
            int idx = tid + t * 256;
            int k = idx >> 7, ii = idx & 127;
            As[k][ii] = g_Xn[b][k0 + k][i0 + ii];
            Bs[k][ii] = g_Yn[b][k0 + k][j0 + ii];
        }
        __syncthreads();
        #pragma unroll
        for (int k = 0; k < 32; k++) {
            float a[8], bb[8];
            *(float4*)&a[0]  = *(const float4*)&As[k][ty*8];
            *(float4*)&a[4]  = *(const float4*)&As[k][ty*8 + 4];
            *(float4*)&bb[0] = *(const float4*)&Bs[k][tx*8];
            *(float4*)&bb[4] = *(const float4*)&Bs[k][tx*8 + 4];
            #pragma unroll
            for (int r = 0; r < 8; r++)
                #pragma unroll
                for (int q = 0; q < 8; q++)
                    acc[r][q] = fmaf(a[r], bb[q], acc[r][q]);
        }
    }

    // epilogue: M = 1-d ; sim += u_i v_j e^{d-1} d  (poly e^d, d in [-1,1])
    const float EINV = 0.36787944117144233f;
    float part = 0.f;
    size_t baseRow = ((size_t)b * HW_ + (i0 + ty*8)) * HW_ + j0 + tx*8;
    #pragma unroll
    for (int r = 0; r < 8; r++) {
        float uu = us[ty*8 + r] * EINV;
        float mv[8];
        #pragma unroll
        for (int q = 0; q < 8; q++) {
            float d = acc[r][q];
            mv[q] = 1.0f - d;
            float e = 2.7557319224e-6f;            // degree-9 Taylor of e^d
            e = fmaf(e, d, 2.4801587302e-5f);
            e = fmaf(e, d, 1.9841269841e-4f);
            e = fmaf(e, d, 1.3888888889e-3f);
            e = fmaf(e, d, 8.3333333333e-3f);
            e = fmaf(e, d, 4.1666666667e-2f);
            e = fmaf(e, d, 1.6666666667e-1f);
            e = fmaf(e, d, 0.5f);
            e = fmaf(e, d, 1.0f);
            e = fmaf(e, d, 1.0f);
            part = fmaf(uu * vs[tx*8 + q] * e, d, part);
        }
        float* po = outM + baseRow + (size_t)r * HW_;
        *(float4*)po       = make_float4(mv[0], mv[1], mv[2], mv[3]);
        *(float4*)(po + 4) = make_float4(mv[4], mv[5], mv[6], mv[7]);
    }

    #pragma unroll
    for (int off = 16; off > 0; off >>= 1)
        part += __shfl_down_sync(0xffffffffu, part, off);
    int lane = tid & 31, warp = tid >> 5;
    if (lane == 0) red[warp] = part;
    __syncthreads();
    if (tid < 8) {
        float p = red[tid];
        #pragma unroll
        for (int off = 4; off > 0; off >>= 1)
            p += __shfl_down_sync(0xffu, p, off);
        if (tid == 0) atomicAdd(&g_sim[b], p);
    }
}

// ---------------- finalize: similarity + L_EMD -----------------------------
__global__ void final_kernel(float* __restrict__ out) {
    int tid = threadIdx.x;
    float s = (tid < B_) ? g_sim[tid] : 0.f;
    if (tid < B_) out[MSIZE + tid] = s;
    float l = (tid < B_) ? (2.0f - 2.0f * s) : 0.f;
    #pragma unroll
    for (int off = 16; off > 0; off >>= 1)
        l += __shfl_down_sync(0xffffffffu, l, off);
    if (tid == 0) out[MSIZE + B_] = l * (1.0f / B_);
}

extern "C" void kernel_launch(void* const* d_in, const int* in_sizes, int n_in,
                              void* d_out, int out_size) {
    const float* X = (const float*)d_in[0];
    const float* Y = (const float*)d_in[1];
    float* out = (float*)d_out;

    init_kernel<<<1, 256>>>();
    norm_kernel<false><<<dim3(18, B_), 256>>>(X);
    norm_kernel<true ><<<dim3(18, B_), 256>>>(Y);
    for (int s = 0; s < 4; s++)
        pass_kernel<<<dim3(9, B_), 256>>>(s);
    gemm_kernel<<<dim3(18, 18, B_), 256>>>(out);
    final_kernel<<<1, 32>>>(out);
}

// round 8
// speedup vs baseline: 1.4316x; 1.4316x over previous
#include <cuda_runtime.h>
#include <cuda_bf16.h>
#include <math.h>
#include <cstdint>

#define B_ 16
#define C_ 64
#define HW_ 2304
#define KEXT 192
#define EPSS 1e-8f
#define NORM_EPS 1e-12f
#define INV_HW (1.0f/2304.0f)
#define MSIZE ((size_t)B_*(size_t)HW_*(size_t)HW_)

// ---------------- scratch (device globals; no runtime allocation) ----------
__device__ float g_Xn[B_][C_][HW_];                 // fp32 normalized, [c][i]
__device__ float g_Yn[B_][C_][HW_];
__device__ __nv_bfloat16 g_Xb[B_][HW_][KEXT];       // [i][k]: [hi(64) | lo(64) | hi(64)]
__device__ __nv_bfloat16 g_Yb[B_][HW_][KEXT];       // [i][k]: [hi(64) | hi(64) | lo(64)]
__device__ float g_u[B_][HW_];
__device__ float g_v[B_][HW_];
__device__ float g_w[4][B_][C_];
__device__ float g_S[B_][4];
__device__ float g_sim[B_];

__device__ __forceinline__ uint32_t smem_u32(const void* p) {
    uint32_t a;
    asm("{ .reg .u64 t; cvta.to.shared.u64 t, %1; cvt.u32.u64 %0, t; }" : "=r"(a) : "l"(p));
    return a;
}

#define LDSM_X4(r, addr) \
    asm volatile("ldmatrix.sync.aligned.m8n8.x4.shared.b16 {%0,%1,%2,%3}, [%4];" \
        : "=r"((r)[0]), "=r"((r)[1]), "=r"((r)[2]), "=r"((r)[3]) : "r"(addr))

#define MMA_BF16(c, a, b0v, b1v) \
    asm volatile("mma.sync.aligned.m16n8k16.row.col.f32.bf16.bf16.f32 " \
        "{%0,%1,%2,%3}, {%4,%5,%6,%7}, {%8,%9}, {%0,%1,%2,%3};" \
        : "+f"((c)[0]), "+f"((c)[1]), "+f"((c)[2]), "+f"((c)[3]) \
        : "r"((a)[0]), "r"((a)[1]), "r"((a)[2]), "r"((a)[3]), "r"(b0v), "r"(b1v))

__device__ __forceinline__ float exp_poly(float d) {
    float e = 2.7557319224e-6f;            // degree-9 Taylor of e^d, d in [-1,1]
    e = fmaf(e, d, 2.4801587302e-5f);
    e = fmaf(e, d, 1.9841269841e-4f);
    e = fmaf(e, d, 1.3888888889e-3f);
    e = fmaf(e, d, 8.3333333333e-3f);
    e = fmaf(e, d, 4.1666666667e-2f);
    e = fmaf(e, d, 1.6666666667e-1f);
    e = fmaf(e, d, 0.5f);
    e = fmaf(e, d, 1.0f);
    e = fmaf(e, d, 1.0f);
    return e;
}

// ---------------- init ------------------------------------------------------
__global__ void init_kernel() {
    int tid = threadIdx.x;
    float* w = &g_w[0][0][0];
    for (int i = tid; i < 4*B_*C_; i += blockDim.x) w[i] = 0.f;
    if (tid < B_*4) (&g_S[0][0])[tid] = 0.f;
    if (tid < B_)   g_sim[tid] = 0.f;
}

// ---------------- normalize + emit fp32 [c][i] and bf16 hi/lo [i][k] -------
template<bool IS_Y>
__global__ void norm_kernel(const float* __restrict__ src) {
    __shared__ float s[C_][129];
    __shared__ float invn[128];
    __shared__ float wacc[C_];
    int b  = blockIdx.y;
    int i0 = blockIdx.x * 128;
    int tid = threadIdx.x;
    if (IS_Y && tid < C_) wacc[tid] = 0.f;

    const float* sp = src + (size_t)b * C_ * HW_ + i0;
    for (int idx = tid; idx < C_*128; idx += 256) {
        int c = idx >> 7, ii = idx & 127;
        s[c][ii] = sp[(size_t)c * HW_ + ii];
    }
    __syncthreads();
    if (tid < 128) {
        float ss = 0.f;
        #pragma unroll
        for (int c = 0; c < C_; c++) { float v = s[c][tid]; ss = fmaf(v, v, ss); }
        invn[tid] = 1.0f / fmaxf(sqrtf(ss), NORM_EPS);
    }
    __syncthreads();

    float (*dst)[HW_] = IS_Y ? g_Yn[b] : g_Xn[b];
    for (int idx = tid; idx < C_*128; idx += 256) {
        int c = idx >> 7, ii = idx & 127;
        float v = s[c][ii] * invn[ii];
        s[c][ii] = v;
        dst[c][i0 + ii] = v;
        if (IS_Y) {
            #pragma unroll
            for (int off = 16; off > 0; off >>= 1)
                v += __shfl_down_sync(0xffffffffu, v, off);
            if ((tid & 31) == 0) atomicAdd(&wacc[c], v);
        }
    }
    __syncthreads();

    // bf16 split, transposed to [i][k]; 8 bf16 (16B) per store
    for (int idx = tid; idx < 128*24; idx += 256) {
        int ii = idx / 24, k0 = (idx % 24) * 8;
        __nv_bfloat16 tmp[8];
        #pragma unroll
        for (int q = 0; q < 8; q++) {
            int k = k0 + q;
            float v = s[k & 63][ii];
            __nv_bfloat16 hi = __float2bfloat16(v);
            int region = k >> 6;                       // 0,1,2
            bool want_lo = IS_Y ? (region == 2) : (region == 1);
            tmp[q] = want_lo ? __float2bfloat16(v - __bfloat162float(hi)) : hi;
        }
        __nv_bfloat16* dp = IS_Y ? &g_Yb[b][i0 + ii][k0] : &g_Xb[b][i0 + ii][k0];
        *(uint4*)dp = *(const uint4*)tmp;
    }

    if (IS_Y) {
        __syncthreads();
        if (tid < C_) atomicAdd(&g_w[0][b][tid], wacc[tid] * INV_HW);
    }
}

// ---------------- Sinkhorn half-step: smem-staged, single global read ------
__global__ void pass_kernel(int stage) {
    extern __shared__ float sm[];            // [64][256]
    __shared__ float ws[C_];
    __shared__ float us[256];
    int b   = blockIdx.y;
    int i0  = blockIdx.x * 256;
    int tid = threadIdx.x;

    const float (*Mat)[HW_]; const float* win;
    float numer, Sval; float* uout; float* wout; float* Sout;
    if (stage == 0)      { Mat = g_Xn[b]; win = g_w[0][b]; numer = 1.f;    Sval = 1.0f;      uout = g_u[b]; wout = g_w[1][b]; Sout = &g_S[b][0]; }
    else if (stage == 1) { Mat = g_Yn[b]; win = g_w[1][b]; numer = 1.f;    Sval = g_S[b][0]; uout = g_v[b]; wout = g_w[2][b]; Sout = &g_S[b][1]; }
    else if (stage == 2) { Mat = g_Xn[b]; win = g_w[2][b]; numer = INV_HW; Sval = g_S[b][1]; uout = g_u[b]; wout = g_w[3][b]; Sout = &g_S[b][2]; }
    else                 { Mat = g_Yn[b]; win = g_w[3][b]; numer = INV_HW; Sval = g_S[b][2]; uout = g_v[b]; wout = nullptr;   Sout = nullptr;    }

    if (tid < C_) ws[tid] = win[tid];

    // stage tile into smem: 64 rows x 256 cols, float4 coalesced, high MLP
    for (int idx = tid; idx < C_ * 64; idx += 256) {
        int c = idx >> 6, t4 = idx & 63;
        float4 v = *(const float4*)&Mat[c][i0 + t4*4];
        *(float4*)&sm[c*256 + t4*4] = v;
    }
    __syncthreads();

    float dot = 0.f;
    #pragma unroll 16
    for (int c = 0; c < C_; c++) dot = fmaf(sm[c*256 + tid], ws[c], dot);
    float u = numer / (Sval - dot + EPSS);
    uout[i0 + tid] = u;
    us[tid] = u;
    __syncthreads();

    if (wout) {
        int warp = tid >> 5, lane = tid & 31;
        #pragma unroll
        for (int c8 = 0; c8 < 8; c8++) {
            int c = warp * 8 + c8;
            float p = 0.f;
            #pragma unroll
            for (int t = 0; t < 8; t++)
                p = fmaf(sm[c*256 + lane + t*32], us[lane + t*32], p);
            #pragma unroll
            for (int off = 16; off > 0; off >>= 1)
                p += __shfl_down_sync(0xffffffffu, p, off);
            if (lane == 0) atomicAdd(&wout[c], p);
        }
        float sv = us[tid];
        #pragma unroll
        for (int off = 16; off > 0; off >>= 1)
            sv += __shfl_down_sync(0xffffffffu, sv, off);
        if (lane == 0) atomicAdd(Sout, sv);
    }
}

// ---------------- mma.sync GEMM: 128x128 tile, K=192 split-bf16 ------------
// smem: [0,512) us | [512,1024) vs | [1024,+51200) A pad200 | [52224,+51200) B
#define SMG_A    1024
#define SMG_B    52224
#define SMG_TOT  103424
#define ROWB     400                   // padded row stride in bytes (200 bf16)

__global__ void __launch_bounds__(256, 2) gemm_kernel(float* __restrict__ outM) {
    extern __shared__ char smem[];
    float* us_s = (float*)smem;
    float* vs_s = (float*)(smem + 512);
    char*  sa   = smem + SMG_A;
    char*  sb_  = smem + SMG_B;
    uint32_t sa_u = smem_u32(sa);
    uint32_t sb_u = smem_u32(sb_);

    int b  = blockIdx.z;
    int i0 = blockIdx.y * 128;
    int j0 = blockIdx.x * 128;
    int tid = threadIdx.x, lane = tid & 31, wid = tid >> 5;

    if (tid < 128) us_s[tid] = g_u[b][i0 + tid];
    else           vs_s[tid - 128] = g_v[b][j0 + tid - 128];

    // stage both tiles: 128 rows x 192 bf16 (24 uint4) each, padded rows
    for (int idx = tid; idx < 6144; idx += 256) {
        int mm = idx >= 3072;
        int p  = mm ? idx - 3072 : idx;
        int r  = p / 24, q = p % 24;
        const uint4* src = ((const uint4*)(mm ? &g_Yb[b][j0 + r][0] : &g_Xb[b][i0 + r][0])) + q;
        *(uint4*)((mm ? sb_ : sa) + r * ROWB + q * 16) = *src;
    }
    __syncthreads();

    int warp_m = (wid & 3) * 32;
    int warp_n = (wid >> 2) * 64;

    // ldmatrix lane addresses (A row-major [m][k]; B is [n][k] = col-major KxN)
    int a_row = warp_m + (lane & 7) + ((lane >> 3) & 1) * 8;
    int a_col = (lane >> 4) * 8;
    uint32_t a_base0 = sa_u + (uint32_t)(a_row * ROWB + a_col * 2);
    uint32_t a_base1 = a_base0 + 16 * ROWB;

    int gg = lane >> 3;
    int b_row = warp_n + (gg >> 1) * 8 + (lane & 7);
    int b_col = (gg & 1) * 8;
    uint32_t b_base = sb_u + (uint32_t)(b_row * ROWB + b_col * 2);

    float acc[2][8][4];
    #pragma unroll
    for (int mi = 0; mi < 2; mi++)
        #pragma unroll
        for (int ni = 0; ni < 8; ni++)
            #pragma unroll
            for (int q = 0; q < 4; q++) acc[mi][ni][q] = 0.f;

    #pragma unroll
    for (int ks = 0; ks < 12; ks++) {
        uint32_t koff = ks * 32;               // 16 bf16 * 2B
        uint32_t af[2][4];
        LDSM_X4(af[0], a_base0 + koff);
        LDSM_X4(af[1], a_base1 + koff);
        uint32_t bf[8][2];
        #pragma unroll
        for (int nb = 0; nb < 4; nb++) {
            uint32_t r4[4];
            LDSM_X4(r4, b_base + nb * 16 * ROWB + koff);
            bf[nb*2    ][0] = r4[0]; bf[nb*2    ][1] = r4[1];
            bf[nb*2 + 1][0] = r4[2]; bf[nb*2 + 1][1] = r4[3];
        }
        #pragma unroll
        for (int mi = 0; mi < 2; mi++)
            #pragma unroll
            for (int ni = 0; ni < 8; ni++)
                MMA_BF16(acc[mi][ni], af[mi], bf[ni][0], bf[ni][1]);
    }

    // epilogue: C frag thread map: c0:(m=t/4, n=2*(t%4)) c1:n+1 c2:m+8 c3:m+8,n+1
    const float EINV = 0.36787944117144233f;
    int tq = lane >> 2;          // row-within-8
    int tr = (lane & 3) * 2;     // col pair base
    float part = 0.f;

    #pragma unroll
    for (int mi = 0; mi < 2; mi++) {
        int r0 = warp_m + mi * 16 + tq;
        int r1 = r0 + 8;
        float uu0 = us_s[r0] * EINV;
        float uu1 = us_s[r1] * EINV;
        float* p0 = outM + ((size_t)b * HW_ + (i0 + r0)) * HW_ + j0 + warp_n;
        float* p1 = outM + ((size_t)b * HW_ + (i0 + r1)) * HW_ + j0 + warp_n;
        #pragma unroll
        for (int ni = 0; ni < 8; ni++) {
            int n0 = ni * 8 + tr;
            float d0 = acc[mi][ni][0], d1 = acc[mi][ni][1];
            float d2 = acc[mi][ni][2], d3 = acc[mi][ni][3];
            float v0 = vs_s[warp_n + n0], v1 = vs_s[warp_n + n0 + 1];
            part = fmaf(uu0 * v0 * exp_poly(d0), d0, part);
            part = fmaf(uu0 * v1 * exp_poly(d1), d1, part);
            part = fmaf(uu1 * v0 * exp_poly(d2), d2, part);
            part = fmaf(uu1 * v1 * exp_poly(d3), d3, part);
            *(float2*)(p0 + n0) = make_float2(1.0f - d0, 1.0f - d1);
            *(float2*)(p1 + n0) = make_float2(1.0f - d2, 1.0f - d3);
        }
    }

    #pragma unroll
    for (int off = 16; off > 0; off >>= 1)
        part += __shfl_down_sync(0xffffffffu, part, off);
    if (lane == 0) atomicAdd(&g_sim[b], part);
}

// ---------------- finalize --------------------------------------------------
__global__ void final_kernel(float* __restrict__ out) {
    int tid = threadIdx.x;
    float s = (tid < B_) ? g_sim[tid] : 0.f;
    if (tid < B_) out[MSIZE + tid] = s;
    float l = (tid < B_) ? (2.0f - 2.0f * s) : 0.f;
    #pragma unroll
    for (int off = 16; off > 0; off >>= 1)
        l += __shfl_down_sync(0xffffffffu, l, off);
    if (tid == 0) out[MSIZE + B_] = l * (1.0f / B_);
}

extern "C" void kernel_launch(void* const* d_in, const int* in_sizes, int n_in,
                              void* d_out, int out_size) {
    const float* X = (const float*)d_in[0];
    const float* Y = (const float*)d_in[1];
    float* out = (float*)d_out;

    // idempotent, deterministic, not stream-ordered: legal during capture
    cudaFuncSetAttribute(pass_kernel, cudaFuncAttributeMaxDynamicSharedMemorySize, 65536);
    cudaFuncSetAttribute(gemm_kernel, cudaFuncAttributeMaxDynamicSharedMemorySize, SMG_TOT);

    init_kernel<<<1, 256>>>();
    norm_kernel<false><<<dim3(18, B_), 256>>>(X);
    norm_kernel<true ><<<dim3(18, B_), 256>>>(Y);
    for (int s = 0; s < 4; s++)
        pass_kernel<<<dim3(9, B_), 256, 65536>>>(s);
    gemm_kernel<<<dim3(18, 18, B_), 256, SMG_TOT>>>(out);
    final_kernel<<<1, 32>>>(out);
}

// round 14
// speedup vs baseline: 1.4388x; 1.0050x over previous
#include <cuda_runtime.h>
#include <cuda_bf16.h>
#include <math.h>
#include <cstdint>

#define B_ 16
#define C_ 64
#define HW_ 2304
#define KEXT 192
#define EPSS 1e-8f
#define NORM_EPS 1e-12f
#define INV_HW (1.0f/2304.0f)
#define MSIZE ((size_t)B_*(size_t)HW_*(size_t)HW_)

typedef unsigned long long u64t;

// ---------------- scratch (device globals; no runtime allocation) ----------
__device__ float g_Xn[B_][C_][HW_];                 // fp32 normalized, [c][i]
__device__ float g_Yn[B_][C_][HW_];
__device__ __nv_bfloat16 g_Xb[B_][HW_][KEXT];       // [i][k]: [hi(64) | lo(64) | hi(64)]
__device__ __nv_bfloat16 g_Yb[B_][HW_][KEXT];       // [i][k]: [hi(64) | hi(64) | lo(64)]
__device__ float g_u[B_][HW_];
__device__ float g_w[4][B_][C_];
__device__ float g_S[B_][4];
__device__ float g_sim[B_];

__device__ __forceinline__ uint32_t smem_u32(const void* p) {
    uint32_t a;
    asm("{ .reg .u64 t; cvta.to.shared.u64 t, %1; cvt.u32.u64 %0, t; }" : "=r"(a) : "l"(p));
    return a;
}

#define LDSM_X4(r, addr) \
    asm volatile("ldmatrix.sync.aligned.m8n8.x4.shared.b16 {%0,%1,%2,%3}, [%4];" \
        : "=r"((r)[0]), "=r"((r)[1]), "=r"((r)[2]), "=r"((r)[3]) : "r"(addr))

#define MMA_BF16(c, a, b0v, b1v) \
    asm volatile("mma.sync.aligned.m16n8k16.row.col.f32.bf16.bf16.f32 " \
        "{%0,%1,%2,%3}, {%4,%5,%6,%7}, {%8,%9}, {%0,%1,%2,%3};" \
        : "+f"((c)[0]), "+f"((c)[1]), "+f"((c)[2]), "+f"((c)[3]) \
        : "r"((a)[0]), "r"((a)[1]), "r"((a)[2]), "r"((a)[3]), "r"(b0v), "r"(b1v))

// packed f32x2 ops (Blackwell baseline; PTX 8.6 sm_100+, no 'a' suffix needed)
#define FMA2(d, a, bb, c) asm("fma.rn.f32x2 %0, %1, %2, %3;" : "=l"(d) : "l"(a), "l"(bb), "l"(c))
#define MUL2(d, a, bb)    asm("mul.rn.f32x2 %0, %1, %2;"     : "=l"(d) : "l"(a), "l"(bb))

__device__ __forceinline__ u64t pack2(float lo, float hi) {
    u64t r; asm("mov.b64 %0, {%1, %2};" : "=l"(r) : "f"(lo), "f"(hi)); return r;
}
__device__ __forceinline__ u64t bcast2(float v) { return pack2(v, v); }

// f(d) = d * e^d via degree-7 e^d poly (|d|<=1; err < 2.5e-5, sim-only)
__device__ __forceinline__ u64t fpoly2(u64t D) {
    u64t p = bcast2(1.0f/5040.0f);
    FMA2(p, p, D, bcast2(1.0f/720.0f));
    FMA2(p, p, D, bcast2(1.0f/120.0f));
    FMA2(p, p, D, bcast2(1.0f/24.0f));
    FMA2(p, p, D, bcast2(1.0f/6.0f));
    FMA2(p, p, D, bcast2(0.5f));
    FMA2(p, p, D, bcast2(1.0f));
    FMA2(p, p, D, bcast2(1.0f));
    MUL2(p, p, D);
    return p;
}

// ---------------- normalize + emit fp32 [c][i] and bf16 hi/lo [i][k] -------
// norm_X (IS_Y=false) also zeroes the per-replay accumulators (block x==0).
template<bool IS_Y>
__global__ void norm_kernel(const float* __restrict__ src) {
    __shared__ float s[C_][129];
    __shared__ float invn[128];
    __shared__ float wacc[C_];
    int b  = blockIdx.y;
    int i0 = blockIdx.x * 128;
    int tid = threadIdx.x;

    if (!IS_Y && blockIdx.x == 0) {
        if (tid < 4*C_) g_w[tid >> 6][b][tid & 63] = 0.f;
        if (tid < 4)    g_S[b][tid] = 0.f;
        if (tid == 0)   g_sim[b] = 0.f;
    }
    if (IS_Y && tid < C_) wacc[tid] = 0.f;

    const float* sp = src + (size_t)b * C_ * HW_ + i0;
    for (int idx = tid; idx < C_*128; idx += 256) {
        int c = idx >> 7, ii = idx & 127;
        s[c][ii] = sp[(size_t)c * HW_ + ii];
    }
    __syncthreads();
    if (tid < 128) {
        float ss = 0.f;
        #pragma unroll
        for (int c = 0; c < C_; c++) { float v = s[c][tid]; ss = fmaf(v, v, ss); }
        invn[tid] = 1.0f / fmaxf(sqrtf(ss), NORM_EPS);
    }
    __syncthreads();

    float (*dst)[HW_] = IS_Y ? g_Yn[b] : g_Xn[b];
    for (int idx = tid; idx < C_*128; idx += 256) {
        int c = idx >> 7, ii = idx & 127;
        float v = s[c][ii] * invn[ii];
        s[c][ii] = v;
        dst[c][i0 + ii] = v;
        if (IS_Y) {
            #pragma unroll
            for (int off = 16; off > 0; off >>= 1)
                v += __shfl_down_sync(0xffffffffu, v, off);
            if ((tid & 31) == 0) atomicAdd(&wacc[c], v);
        }
    }
    __syncthreads();

    // bf16 split, transposed to [i][k]; 8 bf16 (16B) per store
    for (int idx = tid; idx < 128*24; idx += 256) {
        int ii = idx / 24, k0 = (idx % 24) * 8;
        __nv_bfloat16 tmp[8];
        #pragma unroll
        for (int q = 0; q < 8; q++) {
            int k = k0 + q;
            float v = s[k & 63][ii];
            __nv_bfloat16 hi = __float2bfloat16(v);
            int region = k >> 6;
            bool want_lo = IS_Y ? (region == 2) : (region == 1);
            tmp[q] = want_lo ? __float2bfloat16(v - __bfloat162float(hi)) : hi;
        }
        __nv_bfloat16* dp = IS_Y ? &g_Yb[b][i0 + ii][k0] : &g_Xb[b][i0 + ii][k0];
        *(uint4*)dp = *(const uint4*)tmp;
    }

    if (IS_Y) {
        __syncthreads();
        if (tid < C_) atomicAdd(&g_w[0][b][tid], wacc[tid] * INV_HW);
    }
}

// ---------------- Sinkhorn half-step: 128 cols/block, c-split, smem-cached -
// stages 0..2 only (stage 3 = v2 is computed inside gemm_kernel)
__global__ void __launch_bounds__(256) pass_kernel(int stage) {
    __shared__ float tile[C_][128];      // 32 KB
    __shared__ float ws[C_];
    __shared__ float us[128];
    __shared__ float sdot[128];
    int b   = blockIdx.y;
    int i0  = blockIdx.x * 128;
    int tid = threadIdx.x;

    const float (*Mat)[HW_]; const float* win;
    float numer, Sval; float* wout; float* Sout;
    if (stage == 0)      { Mat = g_Xn[b]; win = g_w[0][b]; numer = 1.f;    Sval = 1.0f;      wout = g_w[1][b]; Sout = &g_S[b][0]; }
    else if (stage == 1) { Mat = g_Yn[b]; win = g_w[1][b]; numer = 1.f;    Sval = g_S[b][0]; wout = g_w[2][b]; Sout = &g_S[b][1]; }
    else                 { Mat = g_Xn[b]; win = g_w[2][b]; numer = INV_HW; Sval = g_S[b][1]; wout = g_w[3][b]; Sout = &g_S[b][2]; }

    if (tid < C_) ws[tid] = win[tid];
    __syncthreads();

    int colm  = tid & 127;
    int chalf = (tid >> 7) * 32;
    int col   = i0 + colm;
    float dot = 0.f;
    #pragma unroll
    for (int c = 0; c < 32; c++) {
        float m = Mat[chalf + c][col];
        tile[chalf + c][colm] = m;
        dot = fmaf(m, ws[chalf + c], dot);
    }
    if (tid >= 128) sdot[colm] = dot;
    __syncthreads();
    if (tid < 128) {
        float u = numer / (Sval - (dot + sdot[colm]) + EPSS);
        if (stage == 2) g_u[b][col] = u;   // only u2 is consumed downstream
        us[colm] = u;
    }
    __syncthreads();

    int warp = tid >> 5, lane = tid & 31;
    #pragma unroll
    for (int c8 = 0; c8 < 8; c8++) {
        int c = warp * 8 + c8;
        float p = 0.f;
        #pragma unroll
        for (int t = 0; t < 4; t++)
            p = fmaf(tile[c][lane + t*32], us[lane + t*32], p);
        #pragma unroll
        for (int off = 16; off > 0; off >>= 1)
            p += __shfl_down_sync(0xffffffffu, p, off);
        if (lane == 0) atomicAdd(&wout[c], p);
    }
    if (tid < 128) {
        float sv = us[colm];
        #pragma unroll
        for (int off = 16; off > 0; off >>= 1)
            sv += __shfl_down_sync(0xffffffffu, sv, off);
        if (lane == 0) atomicAdd(Sout, sv);
    }
}

// ---------------- mma.sync GEMM: 128x128 tile, K=192 split-bf16 ------------
// smem: [0,512) us | [512,1024) vs | [1024,1280) w3 | A pad200 | B pad200
#define SMG_W3   1024
#define SMG_A    1280
#define SMG_B    52480
#define SMG_TOT  103680
#define ROWB     400                   // padded row stride in bytes (200 bf16)

__global__ void __launch_bounds__(256, 2) gemm_kernel(float* __restrict__ outM) {
    extern __shared__ char smem[];
    float* us_s = (float*)smem;
    float* vs_s = (float*)(smem + 512);
    float* w3s  = (float*)(smem + SMG_W3);
    char*  sa   = smem + SMG_A;
    char*  sb_  = smem + SMG_B;
    uint32_t sa_u = smem_u32(sa);
    uint32_t sb_u = smem_u32(sb_);

    int b  = blockIdx.z;
    int i0 = blockIdx.y * 128;
    int j0 = blockIdx.x * 128;
    int tid = threadIdx.x, lane = tid & 31, wid = tid >> 5;

    if (tid < 128) us_s[tid] = g_u[b][i0 + tid];
    if (tid < C_)  w3s[tid]  = g_w[3][b][tid];

    // stage both tiles: 128 rows x 192 bf16 (24 uint4) each, padded rows
    for (int idx = tid; idx < 6144; idx += 256) {
        int mm = idx >= 3072;
        int p  = mm ? idx - 3072 : idx;
        int r  = p / 24, q = p % 24;
        const uint4* src = ((const uint4*)(mm ? &g_Yb[b][j0 + r][0] : &g_Xb[b][i0 + r][0])) + q;
        *(uint4*)((mm ? sb_ : sa) + r * ROWB + q * 16) = *src;
    }
    __syncthreads();

    // fused Sinkhorn stage 3: v_j = INV_HW / (S_u2 - Yn[:,j].w3 + eps)
    if (tid >= 128) {
        int j = j0 + tid - 128;
        float S2 = g_S[b][2];
        float dot = 0.f;
        #pragma unroll 16
        for (int c = 0; c < C_; c++) dot = fmaf(g_Yn[b][c][j], w3s[c], dot);
        vs_s[tid - 128] = INV_HW / (S2 - dot + EPSS);
    }

    int warp_m = (wid & 3) * 32;
    int warp_n = (wid >> 2) * 64;

    int a_row = warp_m + (lane & 7) + ((lane >> 3) & 1) * 8;
    int a_col = (lane >> 4) * 8;
    uint32_t a_base0 = sa_u + (uint32_t)(a_row * ROWB + a_col * 2);
    uint32_t a_base1 = a_base0 + 16 * ROWB;

    int gg = lane >> 3;
    int b_row = warp_n + (gg >> 1) * 8 + (lane & 7);
    int b_col = (gg & 1) * 8;
    uint32_t b_base = sb_u + (uint32_t)(b_row * ROWB + b_col * 2);

    float acc[2][8][4];
    #pragma unroll
    for (int mi = 0; mi < 2; mi++)
        #pragma unroll
        for (int ni = 0; ni < 8; ni++)
            #pragma unroll
            for (int q = 0; q < 4; q++) acc[mi][ni][q] = 0.f;

    #pragma unroll
    for (int ks = 0; ks < 12; ks++) {
        uint32_t koff = ks * 32;
        uint32_t af[2][4];
        LDSM_X4(af[0], a_base0 + koff);
        LDSM_X4(af[1], a_base1 + koff);
        uint32_t bfr[8][2];
        #pragma unroll
        for (int nb = 0; nb < 4; nb++) {
            uint32_t r4[4];
            LDSM_X4(r4, b_base + nb * 16 * ROWB + koff);
            bfr[nb*2    ][0] = r4[0]; bfr[nb*2    ][1] = r4[1];
            bfr[nb*2 + 1][0] = r4[2]; bfr[nb*2 + 1][1] = r4[3];
        }
        #pragma unroll
        for (int mi = 0; mi < 2; mi++)
            #pragma unroll
            for (int ni = 0; ni < 8; ni++)
                MMA_BF16(acc[mi][ni], af[mi], bfr[ni][0], bfr[ni][1]);
    }
    __syncthreads();   // vs_s/us_s ready for the epilogue

    // packed f32x2 epilogue: M = 1-d ; sim += u v e^{d-1} d = (u/e) v f(d)
    const float EINV = 0.36787944117144233f;
    const u64t NEG1 = bcast2(-1.0f);
    const u64t ONE  = bcast2(1.0f);
    int tq = lane >> 2;
    int tr = (lane & 3) * 2;
    u64t part2 = bcast2(0.0f);

    #pragma unroll
    for (int mi = 0; mi < 2; mi++) {
        int r0 = warp_m + mi * 16 + tq;
        u64t UU0 = bcast2(us_s[r0] * EINV);
        u64t UU1 = bcast2(us_s[r0 + 8] * EINV);
        float* p0 = outM + ((size_t)b * HW_ + (i0 + r0)) * HW_ + j0 + warp_n;
        float* p1 = p0 + (size_t)8 * HW_;
        #pragma unroll
        for (int ni = 0; ni < 8; ni++) {
            int n0 = ni * 8 + tr;
            float2 vv = *(float2*)&vs_s[warp_n + n0];
            u64t V   = pack2(vv.x, vv.y);
            u64t D01 = pack2(acc[mi][ni][0], acc[mi][ni][1]);
            u64t D23 = pack2(acc[mi][ni][2], acc[mi][ni][3]);
            u64t F01 = fpoly2(D01);
            u64t F23 = fpoly2(D23);
            u64t W;
            MUL2(W, UU0, V);  FMA2(part2, W, F01, part2);
            MUL2(W, UU1, V);  FMA2(part2, W, F23, part2);
            u64t M01, M23;
            FMA2(M01, D01, NEG1, ONE);
            FMA2(M23, D23, NEG1, ONE);
            *(float2*)(p0 + n0) = *(float2*)&M01;
            *(float2*)(p1 + n0) = *(float2*)&M23;
        }
    }

    float plo, phi;
    asm("mov.b64 {%0, %1}, %2;" : "=f"(plo), "=f"(phi) : "l"(part2));
    float part = plo + phi;
    #pragma unroll
    for (int off = 16; off > 0; off >>= 1)
        part += __shfl_down_sync(0xffffffffu, part, off);
    if (lane == 0) atomicAdd(&g_sim[b], part);
}

// ---------------- finalize --------------------------------------------------
__global__ void final_kernel(float* __restrict__ out) {
    int tid = threadIdx.x;
    float s = (tid < B_) ? g_sim[tid] : 0.f;
    if (tid < B_) out[MSIZE + tid] = s;
    float l = (tid < B_) ? (2.0f - 2.0f * s) : 0.f;
    #pragma unroll
    for (int off = 16; off > 0; off >>= 1)
        l += __shfl_down_sync(0xffffffffu, l, off);
    if (tid == 0) out[MSIZE + B_] = l * (1.0f / B_);
}

extern "C" void kernel_launch(void* const* d_in, const int* in_sizes, int n_in,
                              void* d_out, int out_size) {
    const float* X = (const float*)d_in[0];
    const float* Y = (const float*)d_in[1];
    float* out = (float*)d_out;

    cudaFuncSetAttribute(gemm_kernel, cudaFuncAttributeMaxDynamicSharedMemorySize, SMG_TOT);

    norm_kernel<false><<<dim3(18, B_), 256>>>(X);
    norm_kernel<true ><<<dim3(18, B_), 256>>>(Y);
    pass_kernel<<<dim3(18, B_), 256>>>(0);
    pass_kernel<<<dim3(18, B_), 256>>>(1);
    pass_kernel<<<dim3(18, B_), 256>>>(2);
    gemm_kernel<<<dim3(18, 18, B_), 256, SMG_TOT>>>(out);   // launch #6 -> ncu target
    final_kernel<<<1, 32>>>(out);
}

// round 15
// speedup vs baseline: 1.5526x; 1.0791x over previous
#include <cuda_runtime.h>
#include <cuda_bf16.h>
#include <math.h>
#include <cstdint>

#define B_ 16
#define C_ 64
#define HW_ 2304
#define EPSS 1e-8f
#define NORM_EPS 1e-12f
#define INV_HW (1.0f/2304.0f)
#define MSIZE ((size_t)B_*(size_t)HW_*(size_t)HW_)

typedef unsigned long long u64t;

// ---------------- scratch (device globals; no runtime allocation) ----------
__device__ float g_Xn[B_][C_][HW_];                 // fp32 normalized, [c][i]
__device__ float g_Yn[B_][C_][HW_];
__device__ __nv_bfloat16 g_Xb[B_][HW_][128];        // [i][k]: [hi(64) | lo(64)]
__device__ __nv_bfloat16 g_Yb[B_][HW_][64];         // [i][k]: [hi(64)]
__device__ float g_u[B_][HW_];
__device__ float g_v[B_][HW_];
__device__ float g_w[4][B_][C_];
__device__ float g_S[B_][4];
__device__ float g_sim[B_];

__device__ __forceinline__ uint32_t smem_u32(const void* p) {
    uint32_t a;
    asm("{ .reg .u64 t; cvta.to.shared.u64 t, %1; cvt.u32.u64 %0, t; }" : "=r"(a) : "l"(p));
    return a;
}

#define LDSM_X4(r, addr) \
    asm volatile("ldmatrix.sync.aligned.m8n8.x4.shared.b16 {%0,%1,%2,%3}, [%4];" \
        : "=r"((r)[0]), "=r"((r)[1]), "=r"((r)[2]), "=r"((r)[3]) : "r"(addr))

#define MMA_BF16(c, a, b0v, b1v) \
    asm volatile("mma.sync.aligned.m16n8k16.row.col.f32.bf16.bf16.f32 " \
        "{%0,%1,%2,%3}, {%4,%5,%6,%7}, {%8,%9}, {%0,%1,%2,%3};" \
        : "+f"((c)[0]), "+f"((c)[1]), "+f"((c)[2]), "+f"((c)[3]) \
        : "r"((a)[0]), "r"((a)[1]), "r"((a)[2]), "r"((a)[3]), "r"(b0v), "r"(b1v))

// packed f32x2 ops
#define FMA2(d, a, bb, c) asm("fma.rn.f32x2 %0, %1, %2, %3;" : "=l"(d) : "l"(a), "l"(bb), "l"(c))
#define MUL2(d, a, bb)    asm("mul.rn.f32x2 %0, %1, %2;"     : "=l"(d) : "l"(a), "l"(bb))

__device__ __forceinline__ u64t pack2(float lo, float hi) {
    u64t r; asm("mov.b64 %0, {%1, %2};" : "=l"(r) : "f"(lo), "f"(hi)); return r;
}
__device__ __forceinline__ u64t bcast2(float v) { return pack2(v, v); }

// f(d) = d * e^d via degree-7 e^d poly (|d|<=1)
__device__ __forceinline__ u64t fpoly2(u64t D) {
    u64t p = bcast2(1.0f/5040.0f);
    FMA2(p, p, D, bcast2(1.0f/720.0f));
    FMA2(p, p, D, bcast2(1.0f/120.0f));
    FMA2(p, p, D, bcast2(1.0f/24.0f));
    FMA2(p, p, D, bcast2(1.0f/6.0f));
    FMA2(p, p, D, bcast2(0.5f));
    FMA2(p, p, D, bcast2(1.0f));
    FMA2(p, p, D, bcast2(1.0f));
    MUL2(p, p, D);
    return p;
}

// ---------------- normalize + emit fp32 [c][i] and bf16 [i][k] -------------
template<bool IS_Y>
__global__ void norm_kernel(const float* __restrict__ src) {
    __shared__ float s[C_][129];
    __shared__ float invn[128];
    __shared__ float wacc[C_];
    int b  = blockIdx.y;
    int i0 = blockIdx.x * 128;
    int tid = threadIdx.x;

    if (!IS_Y && blockIdx.x == 0) {
        if (tid < 4*C_) g_w[tid >> 6][b][tid & 63] = 0.f;
        if (tid < 4)    g_S[b][tid] = 0.f;
        if (tid == 0)   g_sim[b] = 0.f;
    }
    if (IS_Y && tid < C_) wacc[tid] = 0.f;

    const float* sp = src + (size_t)b * C_ * HW_ + i0;
    for (int idx = tid; idx < C_*128; idx += 256) {
        int c = idx >> 7, ii = idx & 127;
        s[c][ii] = sp[(size_t)c * HW_ + ii];
    }
    __syncthreads();
    if (tid < 128) {
        float ss = 0.f;
        #pragma unroll
        for (int c = 0; c < C_; c++) { float v = s[c][tid]; ss = fmaf(v, v, ss); }
        invn[tid] = 1.0f / fmaxf(sqrtf(ss), NORM_EPS);
    }
    __syncthreads();

    float (*dst)[HW_] = IS_Y ? g_Yn[b] : g_Xn[b];
    for (int idx = tid; idx < C_*128; idx += 256) {
        int c = idx >> 7, ii = idx & 127;
        float v = s[c][ii] * invn[ii];
        s[c][ii] = v;
        dst[c][i0 + ii] = v;
        if (IS_Y) {
            #pragma unroll
            for (int off = 16; off > 0; off >>= 1)
                v += __shfl_down_sync(0xffffffffu, v, off);
            if ((tid & 31) == 0) atomicAdd(&wacc[c], v);
        }
    }
    __syncthreads();

    // bf16 emit, transposed to [i][k]; X: [hi|lo] (16 chunks), Y: [hi] (8 chunks)
    const int CH = IS_Y ? 8 : 16;
    for (int idx = tid; idx < 128*CH; idx += 256) {
        int ii = idx / CH, k0 = (idx % CH) * 8;
        __nv_bfloat16 tmp[8];
        #pragma unroll
        for (int q = 0; q < 8; q++) {
            int k = k0 + q;
            float v = s[k & 63][ii];
            __nv_bfloat16 hi = __float2bfloat16(v);
            bool want_lo = (!IS_Y) && (k >= 64);
            tmp[q] = want_lo ? __float2bfloat16(v - __bfloat162float(hi)) : hi;
        }
        __nv_bfloat16* dp = IS_Y ? &g_Yb[b][i0 + ii][k0] : &g_Xb[b][i0 + ii][k0];
        *(uint4*)dp = *(const uint4*)tmp;
    }

    if (IS_Y) {
        __syncthreads();
        if (tid < C_) atomicAdd(&g_w[0][b][tid], wacc[tid] * INV_HW);
    }
}

// ---------------- Sinkhorn half-step (stages 0..3) --------------------------
__global__ void __launch_bounds__(256) pass_kernel(int stage) {
    __shared__ float tile[C_][128];      // 32 KB
    __shared__ float ws[C_];
    __shared__ float us[128];
    __shared__ float sdot[128];
    int b   = blockIdx.y;
    int i0  = blockIdx.x * 128;
    int tid = threadIdx.x;

    const float (*Mat)[HW_]; const float* win;
    float numer, Sval; float* uout; float* wout; float* Sout;
    if (stage == 0)      { Mat = g_Xn[b]; win = g_w[0][b]; numer = 1.f;    Sval = 1.0f;      uout = nullptr; wout = g_w[1][b]; Sout = &g_S[b][0]; }
    else if (stage == 1) { Mat = g_Yn[b]; win = g_w[1][b]; numer = 1.f;    Sval = g_S[b][0]; uout = nullptr; wout = g_w[2][b]; Sout = &g_S[b][1]; }
    else if (stage == 2) { Mat = g_Xn[b]; win = g_w[2][b]; numer = INV_HW; Sval = g_S[b][1]; uout = g_u[b];  wout = g_w[3][b]; Sout = &g_S[b][2]; }
    else                 { Mat = g_Yn[b]; win = g_w[3][b]; numer = INV_HW; Sval = g_S[b][2]; uout = g_v[b];  wout = nullptr;   Sout = nullptr;    }

    if (tid < C_) ws[tid] = win[tid];
    __syncthreads();

    int colm  = tid & 127;
    int chalf = (tid >> 7) * 32;
    int col   = i0 + colm;
    float dot = 0.f;
    #pragma unroll
    for (int c = 0; c < 32; c++) {
        float m = Mat[chalf + c][col];
        tile[chalf + c][colm] = m;
        dot = fmaf(m, ws[chalf + c], dot);
    }
    if (tid >= 128) sdot[colm] = dot;
    __syncthreads();
    if (tid < 128) {
        float u = numer / (Sval - (dot + sdot[colm]) + EPSS);
        if (uout) uout[col] = u;
        us[colm] = u;
    }
    __syncthreads();

    if (wout) {
        int warp = tid >> 5, lane = tid & 31;
        #pragma unroll
        for (int c8 = 0; c8 < 8; c8++) {
            int c = warp * 8 + c8;
            float p = 0.f;
            #pragma unroll
            for (int t = 0; t < 4; t++)
                p = fmaf(tile[c][lane + t*32], us[lane + t*32], p);
            #pragma unroll
            for (int off = 16; off > 0; off >>= 1)
                p += __shfl_down_sync(0xffffffffu, p, off);
            if (lane == 0) atomicAdd(&wout[c], p);
        }
        if (tid < 128) {
            float sv = us[colm];
            int lane2 = tid & 31;
            #pragma unroll
            for (int off = 16; off > 0; off >>= 1)
                sv += __shfl_down_sync(0xffffffffu, sv, off);
            if (lane2 == 0) atomicAdd(Sout, sv);
        }
    }
}

// ---------------- mma.sync GEMM: 128x128 tile, K=128 ------------------------
// d = x . bf16(y) :  A=[Xhi|Xlo], B=[Yhi|Yhi]
// smem: [0,512) us | [512,1024) vs | A pad272 | B pad272
#define SMG_A    1024
#define SMG_B    35840                 // 1024 + 128*272
#define SMG_TOT  70656                 // 35840 + 128*272
#define ROWB     272                   // 128 bf16 + 16B pad (68 words ≡ 4 banks)

__global__ void __launch_bounds__(256, 2) gemm_kernel(float* __restrict__ outM) {
    extern __shared__ char smem[];
    float* us_s = (float*)smem;
    float* vs_s = (float*)(smem + 512);
    char*  sa   = smem + SMG_A;
    char*  sb_  = smem + SMG_B;
    uint32_t sa_u = smem_u32(sa);
    uint32_t sb_u = smem_u32(sb_);

    int b  = blockIdx.z;
    int i0 = blockIdx.y * 128;
    int j0 = blockIdx.x * 128;
    int tid = threadIdx.x, lane = tid & 31, wid = tid >> 5;

    if (tid < 128) us_s[tid] = g_u[b][i0 + tid];
    else           vs_s[tid - 128] = g_v[b][j0 + tid - 128];

    // stage tiles: A 128 rows x 16 chunks; B 128 rows x 8 src chunks (dup'd)
    for (int idx = tid; idx < 3072; idx += 256) {
        if (idx < 2048) {
            int r = idx >> 4, q = idx & 15;
            uint4 val = ((const uint4*)&g_Xb[b][i0 + r][0])[q];
            *(uint4*)(sa + r * ROWB + q * 16) = val;
        } else {
            int p = idx - 2048;
            int r = p >> 3, q = p & 7;
            uint4 val = ((const uint4*)&g_Yb[b][j0 + r][0])[q];
            *(uint4*)(sb_ + r * ROWB + q * 16) = val;
            *(uint4*)(sb_ + r * ROWB + 128 + q * 16) = val;
        }
    }
    __syncthreads();

    int warp_m = (wid & 3) * 32;
    int warp_n = (wid >> 2) * 64;

    int a_row = warp_m + (lane & 7) + ((lane >> 3) & 1) * 8;
    int a_col = (lane >> 4) * 8;
    uint32_t a_base0 = sa_u + (uint32_t)(a_row * ROWB + a_col * 2);
    uint32_t a_base1 = a_base0 + 16 * ROWB;

    int gg = lane >> 3;
    int b_row = warp_n + (gg >> 1) * 8 + (lane & 7);
    int b_col = (gg & 1) * 8;
    uint32_t b_base = sb_u + (uint32_t)(b_row * ROWB + b_col * 2);

    float acc[2][8][4];
    #pragma unroll
    for (int mi = 0; mi < 2; mi++)
        #pragma unroll
        for (int ni = 0; ni < 8; ni++)
            #pragma unroll
            for (int q = 0; q < 4; q++) acc[mi][ni][q] = 0.f;

    #pragma unroll
    for (int ks = 0; ks < 8; ks++) {
        uint32_t koff = ks * 32;               // 16 bf16 * 2B
        uint32_t af[2][4];
        LDSM_X4(af[0], a_base0 + koff);
        LDSM_X4(af[1], a_base1 + koff);
        uint32_t bfr[8][2];
        #pragma unroll
        for (int nb = 0; nb < 4; nb++) {
            uint32_t r4[4];
            LDSM_X4(r4, b_base + nb * 16 * ROWB + koff);
            bfr[nb*2    ][0] = r4[0]; bfr[nb*2    ][1] = r4[1];
            bfr[nb*2 + 1][0] = r4[2]; bfr[nb*2 + 1][1] = r4[3];
        }
        #pragma unroll
        for (int mi = 0; mi < 2; mi++)
            #pragma unroll
            for (int ni = 0; ni < 8; ni++)
                MMA_BF16(acc[mi][ni], af[mi], bfr[ni][0], bfr[ni][1]);
    }
    __syncthreads();

    // packed f32x2 epilogue: M = 1-d ; sim += (u/e) v f(d)
    const float EINV = 0.36787944117144233f;
    const u64t NEG1 = bcast2(-1.0f);
    const u64t ONE  = bcast2(1.0f);
    int tq = lane >> 2;
    int tr = (lane & 3) * 2;
    u64t part2 = bcast2(0.0f);

    #pragma unroll
    for (int mi = 0; mi < 2; mi++) {
        int r0 = warp_m + mi * 16 + tq;
        u64t UU0 = bcast2(us_s[r0] * EINV);
        u64t UU1 = bcast2(us_s[r0 + 8] * EINV);
        float* p0 = outM + ((size_t)b * HW_ + (i0 + r0)) * HW_ + j0 + warp_n;
        float* p1 = p0 + (size_t)8 * HW_;
        #pragma unroll
        for (int ni = 0; ni < 8; ni++) {
            int n0 = ni * 8 + tr;
            float2 vv = *(float2*)&vs_s[warp_n + n0];
            u64t V   = pack2(vv.x, vv.y);
            u64t D01 = pack2(acc[mi][ni][0], acc[mi][ni][1]);
            u64t D23 = pack2(acc[mi][ni][2], acc[mi][ni][3]);
            u64t F01 = fpoly2(D01);
            u64t F23 = fpoly2(D23);
            u64t W;
            MUL2(W, UU0, V);  FMA2(part2, W, F01, part2);
            MUL2(W, UU1, V);  FMA2(part2, W, F23, part2);
            u64t M01, M23;
            FMA2(M01, D01, NEG1, ONE);
            FMA2(M23, D23, NEG1, ONE);
            *(float2*)(p0 + n0) = *(float2*)&M01;
            *(float2*)(p1 + n0) = *(float2*)&M23;
        }
    }

    float plo, phi;
    asm("mov.b64 {%0, %1}, %2;" : "=f"(plo), "=f"(phi) : "l"(part2));
    float part = plo + phi;
    #pragma unroll
    for (int off = 16; off > 0; off >>= 1)
        part += __shfl_down_sync(0xffffffffu, part, off);
    if (lane == 0) atomicAdd(&g_sim[b], part);
}

// ---------------- finalize --------------------------------------------------
__global__ void final_kernel(float* __restrict__ out) {
    int tid = threadIdx.x;
    float s = (tid < B_) ? g_sim[tid] : 0.f;
    if (tid < B_) out[MSIZE + tid] = s;
    float l = (tid < B_) ? (2.0f - 2.0f * s) : 0.f;
    #pragma unroll
    for (int off = 16; off > 0; off >>= 1)
        l += __shfl_down_sync(0xffffffffu, l, off);
    if (tid == 0) out[MSIZE + B_] = l * (1.0f / B_);
}

extern "C" void kernel_launch(void* const* d_in, const int* in_sizes, int n_in,
                              void* d_out, int out_size) {
    const float* X = (const float*)d_in[0];
    const float* Y = (const float*)d_in[1];
    float* out = (float*)d_out;

    cudaFuncSetAttribute(gemm_kernel, cudaFuncAttributeMaxDynamicSharedMemorySize, SMG_TOT);

    norm_kernel<false><<<dim3(18, B_), 256>>>(X);
    norm_kernel<true ><<<dim3(18, B_), 256>>>(Y);
    pass_kernel<<<dim3(18, B_), 256>>>(0);
    pass_kernel<<<dim3(18, B_), 256>>>(1);
    pass_kernel<<<dim3(18, B_), 256>>>(2);
    pass_kernel<<<dim3(18, B_), 256>>>(3);
    gemm_kernel<<<dim3(18, 18, B_), 256, SMG_TOT>>>(out);
    final_kernel<<<1, 32>>>(out);
}

// round 17
// speedup vs baseline: 2.0896x; 1.3459x over previous
#include <cuda_runtime.h>
#include <cuda_bf16.h>
#include <math.h>
#include <cstdint>

#define B_ 16
#define C_ 64
#define HW_ 2304
#define EPSS 1e-8f
#define NORM_EPS 1e-12f
#define INV_HW (1.0f/2304.0f)
#define MSIZE ((size_t)B_*(size_t)HW_*(size_t)HW_)
#define NJT 18

typedef unsigned long long u64t;

// ---------------- scratch (device globals; no runtime allocation) ----------
__device__ float g_Xn[B_][C_][HW_];                 // fp32 normalized, [c][i]
__device__ float g_Yn[B_][C_][HW_];
__device__ __nv_bfloat16 g_Xb[B_][HW_][128];        // [i][k]: [hi(64) | lo(64)]
__device__ __nv_bfloat16 g_Yb[B_][HW_][64];         // [i][k]: [hi(64)]
__device__ float g_u[B_][HW_];
__device__ float g_v[B_][HW_];
__device__ float g_w[4][B_][C_];
__device__ float g_S[B_][4];
__device__ float g_sim[B_];

__device__ __forceinline__ uint32_t smem_u32(const void* p) {
    uint32_t a;
    asm("{ .reg .u64 t; cvta.to.shared.u64 t, %1; cvt.u32.u64 %0, t; }" : "=r"(a) : "l"(p));
    return a;
}

#define LDSM_X4(r, addr) \
    asm volatile("ldmatrix.sync.aligned.m8n8.x4.shared.b16 {%0,%1,%2,%3}, [%4];" \
        : "=r"((r)[0]), "=r"((r)[1]), "=r"((r)[2]), "=r"((r)[3]) : "r"(addr))

#define MMA_BF16(c, a, b0v, b1v) \
    asm volatile("mma.sync.aligned.m16n8k16.row.col.f32.bf16.bf16.f32 " \
        "{%0,%1,%2,%3}, {%4,%5,%6,%7}, {%8,%9}, {%0,%1,%2,%3};" \
        : "+f"((c)[0]), "+f"((c)[1]), "+f"((c)[2]), "+f"((c)[3]) \
        : "r"((a)[0]), "r"((a)[1]), "r"((a)[2]), "r"((a)[3]), "r"(b0v), "r"(b1v))

// cp.async (sm_80+)
#define CP_ASYNC16(dst, src) asm volatile("cp.async.ca.shared.global [%0], [%1], 16;" :: "r"(dst), "l"(src))
#define CP_COMMIT()          asm volatile("cp.async.commit_group;" ::: "memory")
#define CP_WAIT0()           asm volatile("cp.async.wait_group 0;" ::: "memory")

// packed f32x2 ops
#define FMA2(d, a, bb, c) asm("fma.rn.f32x2 %0, %1, %2, %3;" : "=l"(d) : "l"(a), "l"(bb), "l"(c))
#define MUL2(d, a, bb)    asm("mul.rn.f32x2 %0, %1, %2;"     : "=l"(d) : "l"(a), "l"(bb))

__device__ __forceinline__ u64t pack2(float lo, float hi) {
    u64t r; asm("mov.b64 %0, {%1, %2};" : "=l"(r) : "f"(lo), "f"(hi)); return r;
}
__device__ __forceinline__ u64t bcast2(float v) { return pack2(v, v); }

// f(d) = d * e^d via degree-7 e^d poly (|d|<=1)
__device__ __forceinline__ u64t fpoly2(u64t D) {
    u64t p = bcast2(1.0f/5040.0f);
    FMA2(p, p, D, bcast2(1.0f/720.0f));
    FMA2(p, p, D, bcast2(1.0f/120.0f));
    FMA2(p, p, D, bcast2(1.0f/24.0f));
    FMA2(p, p, D, bcast2(1.0f/6.0f));
    FMA2(p, p, D, bcast2(0.5f));
    FMA2(p, p, D, bcast2(1.0f));
    FMA2(p, p, D, bcast2(1.0f));
    MUL2(p, p, D);
    return p;
}

// ---------------- normalize + emit fp32 [c][i] and bf16 [i][k] -------------
template<bool IS_Y>
__global__ void norm_kernel(const float* __restrict__ src) {
    __shared__ float s[C_][129];
    __shared__ float invn[128];
    __shared__ float wacc[C_];
    int b  = blockIdx.y;
    int i0 = blockIdx.x * 128;
    int tid = threadIdx.x;

    if (!IS_Y && blockIdx.x == 0) {
        if (tid < 4*C_) g_w[tid >> 6][b][tid & 63] = 0.f;
        if (tid < 4)    g_S[b][tid] = 0.f;
        if (tid == 0)   g_sim[b] = 0.f;
    }
    if (IS_Y && tid < C_) wacc[tid] = 0.f;

    const float* sp = src + (size_t)b * C_ * HW_ + i0;
    for (int idx = tid; idx < C_*128; idx += 256) {
        int c = idx >> 7, ii = idx & 127;
        s[c][ii] = sp[(size_t)c * HW_ + ii];
    }
    __syncthreads();
    if (tid < 128) {
        float ss = 0.f;
        #pragma unroll
        for (int c = 0; c < C_; c++) { float v = s[c][tid]; ss = fmaf(v, v, ss); }
        invn[tid] = 1.0f / fmaxf(sqrtf(ss), NORM_EPS);
    }
    __syncthreads();

    float (*dst)[HW_] = IS_Y ? g_Yn[b] : g_Xn[b];
    for (int idx = tid; idx < C_*128; idx += 256) {
        int c = idx >> 7, ii = idx & 127;
        float v = s[c][ii] * invn[ii];
        s[c][ii] = v;
        dst[c][i0 + ii] = v;
        if (IS_Y) {
            #pragma unroll
            for (int off = 16; off > 0; off >>= 1)
                v += __shfl_down_sync(0xffffffffu, v, off);
            if ((tid & 31) == 0) atomicAdd(&wacc[c], v);
        }
    }
    __syncthreads();

    const int CH = IS_Y ? 8 : 16;
    for (int idx = tid; idx < 128*CH; idx += 256) {
        int ii = idx / CH, k0 = (idx % CH) * 8;
        __nv_bfloat16 tmp[8];
        #pragma unroll
        for (int q = 0; q < 8; q++) {
            int k = k0 + q;
            float v = s[k & 63][ii];
            __nv_bfloat16 hi = __float2bfloat16(v);
            bool want_lo = (!IS_Y) && (k >= 64);
            tmp[q] = want_lo ? __float2bfloat16(v - __bfloat162float(hi)) : hi;
        }
        __nv_bfloat16* dp = IS_Y ? &g_Yb[b][i0 + ii][k0] : &g_Xb[b][i0 + ii][k0];
        *(uint4*)dp = *(const uint4*)tmp;
    }

    if (IS_Y) {
        __syncthreads();
        if (tid < C_) atomicAdd(&g_w[0][b][tid], wacc[tid] * INV_HW);
    }
}

// ---------------- Sinkhorn half-step (stages 0..3) --------------------------
__global__ void __launch_bounds__(256) pass_kernel(int stage) {
    __shared__ float tile[C_][128];
    __shared__ float ws[C_];
    __shared__ float us[128];
    __shared__ float sdot[128];
    int b   = blockIdx.y;
    int i0  = blockIdx.x * 128;
    int tid = threadIdx.x;

    const float (*Mat)[HW_]; const float* win;
    float numer, Sval; float* uout; float* wout; float* Sout;
    if (stage == 0)      { Mat = g_Xn[b]; win = g_w[0][b]; numer = 1.f;    Sval = 1.0f;      uout = nullptr; wout = g_w[1][b]; Sout = &g_S[b][0]; }
    else if (stage == 1) { Mat = g_Yn[b]; win = g_w[1][b]; numer = 1.f;    Sval = g_S[b][0]; uout = nullptr; wout = g_w[2][b]; Sout = &g_S[b][1]; }
    else if (stage == 2) { Mat = g_Xn[b]; win = g_w[2][b]; numer = INV_HW; Sval = g_S[b][1]; uout = g_u[b];  wout = g_w[3][b]; Sout = &g_S[b][2]; }
    else                 { Mat = g_Yn[b]; win = g_w[3][b]; numer = INV_HW; Sval = g_S[b][2]; uout = g_v[b];  wout = nullptr;   Sout = nullptr;    }

    if (tid < C_) ws[tid] = win[tid];
    __syncthreads();

    int colm  = tid & 127;
    int chalf = (tid >> 7) * 32;
    int col   = i0 + colm;
    float dot = 0.f;
    #pragma unroll
    for (int c = 0; c < 32; c++) {
        float m = Mat[chalf + c][col];
        tile[chalf + c][colm] = m;
        dot = fmaf(m, ws[chalf + c], dot);
    }
    if (tid >= 128) sdot[colm] = dot;
    __syncthreads();
    if (tid < 128) {
        float u = numer / (Sval - (dot + sdot[colm]) + EPSS);
        if (uout) uout[col] = u;
        us[colm] = u;
    }
    __syncthreads();

    if (wout) {
        int warp = tid >> 5, lane = tid & 31;
        #pragma unroll
        for (int c8 = 0; c8 < 8; c8++) {
            int c = warp * 8 + c8;
            float p = 0.f;
            #pragma unroll
            for (int t = 0; t < 4; t++)
                p = fmaf(tile[c][lane + t*32], us[lane + t*32], p);
            #pragma unroll
            for (int off = 16; off > 0; off >>= 1)
                p += __shfl_down_sync(0xffffffffu, p, off);
            if (lane == 0) atomicAdd(&wout[c], p);
        }
        if (tid < 128) {
            float sv = us[colm];
            int lane2 = tid & 31;
            #pragma unroll
            for (int off = 16; off > 0; off >>= 1)
                sv += __shfl_down_sync(0xffffffffu, sv, off);
            if (lane2 == 0) atomicAdd(Sout, sv);
        }
    }
}

// ---------------- persistent-i GEMM: A resident, B double-buffered ---------
// d = x . bf16(y) : A=[Xhi|Xlo] (K=128), B=[Yhi] (K=64, reused for both halves)
// smem: [0,512) us | [512,1024) vs | A 128xROWB_A | B0 | B1 (128xROWB_B each)
#define ROWB_A   272                   // 68 words ≡ 4 banks mod 32
#define ROWB_B   144                   // 36 words ≡ 4 banks mod 32
#define SMG_A    1024
#define SMG_B0   (SMG_A + 128*ROWB_A)          // 35840
#define SMG_B1   (SMG_B0 + 128*ROWB_B)         // 54272
#define SMG_TOT  (SMG_B1 + 128*ROWB_B)         // 72704

__global__ void __launch_bounds__(256, 2) gemm_kernel(float* __restrict__ outM) {
    extern __shared__ char smem[];
    float* us_s = (float*)smem;
    float* vs_s = (float*)(smem + 512);
    char*  sa   = smem + SMG_A;
    uint32_t sa_u  = smem_u32(sa);
    uint32_t sb0_u = sa_u + 128*ROWB_A;

    int b  = blockIdx.y;
    int i0 = blockIdx.x * 128;
    int tid = threadIdx.x, lane = tid & 31, wid = tid >> 5;

    if (tid < 128) us_s[tid] = g_u[b][i0 + tid];

    // A tile staged once: 128 rows x 16 chunks (uint4)
    for (int idx = tid; idx < 2048; idx += 256) {
        int r = idx >> 4, q = idx & 15;
        uint4 val = ((const uint4*)&g_Xb[b][i0 + r][0])[q];
        *(uint4*)(sa + r * ROWB_A + q * 16) = val;
    }

    // prefetch B[0] into buf0
    {
        uint32_t dst = sb0_u;
        for (int idx = tid; idx < 1024; idx += 256) {
            int r = idx >> 3, q = idx & 7;
            CP_ASYNC16(dst + r * ROWB_B + q * 16, (const char*)&g_Yb[b][r][q * 8]);
        }
        CP_COMMIT();
    }

    int warp_m = (wid & 3) * 32;
    int warp_n = (wid >> 2) * 64;

    int a_row = warp_m + (lane & 7) + ((lane >> 3) & 1) * 8;
    int a_col = (lane >> 4) * 8;
    uint32_t a_base0 = sa_u + (uint32_t)(a_row * ROWB_A + a_col * 2);
    uint32_t a_base1 = a_base0 + 16 * ROWB_A;

    int gg = lane >> 3;
    int b_roff = (warp_n + (gg >> 1) * 8 + (lane & 7)) * ROWB_B + ((gg & 1) * 8) * 2;

    const float EINV = 0.36787944117144233f;
    const u64t NEG1 = bcast2(-1.0f);
    const u64t ONE  = bcast2(1.0f);
    int tq = lane >> 2;
    int tr = (lane & 3) * 2;

    for (int j = 0; j < NJT; j++) {
        int j0 = j * 128;
        CP_WAIT0();
        __syncthreads();                       // B[j] visible; prev epilogue done

        if (tid < 128) vs_s[tid] = g_v[b][j0 + tid];

        if (j + 1 < NJT) {                     // prefetch B[j+1] into other buffer
            uint32_t dst = sb0_u + ((j + 1) & 1) * (128 * ROWB_B);
            int jn0 = j0 + 128;
            for (int idx = tid; idx < 1024; idx += 256) {
                int r = idx >> 3, q = idx & 7;
                CP_ASYNC16(dst + r * ROWB_B + q * 16, (const char*)&g_Yb[b][jn0 + r][q * 8]);
            }
            CP_COMMIT();
        }

        uint32_t b_base = sb0_u + (j & 1) * (128 * ROWB_B) + (uint32_t)b_roff;

        float acc[2][8][4];
        #pragma unroll
        for (int mi = 0; mi < 2; mi++)
            #pragma unroll
            for (int ni = 0; ni < 8; ni++)
                #pragma unroll
                for (int q = 0; q < 4; q++) acc[mi][ni][q] = 0.f;

        #pragma unroll
        for (int ks = 0; ks < 8; ks++) {
            uint32_t akoff = ks * 32;
            uint32_t bkoff = (ks & 3) * 32;    // B K=64, reused for Xhi and Xlo
            uint32_t af[2][4];
            LDSM_X4(af[0], a_base0 + akoff);
            LDSM_X4(af[1], a_base1 + akoff);
            uint32_t bfr[8][2];
            #pragma unroll
            for (int nb = 0; nb < 4; nb++) {
                uint32_t r4[4];
                LDSM_X4(r4, b_base + nb * 16 * ROWB_B + bkoff);
                bfr[nb*2    ][0] = r4[0]; bfr[nb*2    ][1] = r4[1];
                bfr[nb*2 + 1][0] = r4[2]; bfr[nb*2 + 1][1] = r4[3];
            }
            #pragma unroll
            for (int mi = 0; mi < 2; mi++)
                #pragma unroll
                for (int ni = 0; ni < 8; ni++)
                    MMA_BF16(acc[mi][ni], af[mi], bfr[ni][0], bfr[ni][1]);
        }
        __syncthreads();                       // vs_s writes visible for epilogue

        u64t part2 = bcast2(0.0f);
        #pragma unroll
        for (int mi = 0; mi < 2; mi++) {
            int r0 = warp_m + mi * 16 + tq;
            u64t UU0 = bcast2(us_s[r0] * EINV);
            u64t UU1 = bcast2(us_s[r0 + 8] * EINV);
            float* p0 = outM + ((size_t)b * HW_ + (i0 + r0)) * HW_ + j0 + warp_n;
            float* p1 = p0 + (size_t)8 * HW_;
            #pragma unroll
            for (int ni = 0; ni < 8; ni++) {
                int n0 = ni * 8 + tr;
                float2 vv = *(float2*)&vs_s[warp_n + n0];
                u64t V   = pack2(vv.x, vv.y);
                u64t D01 = pack2(acc[mi][ni][0], acc[mi][ni][1]);
                u64t D23 = pack2(acc[mi][ni][2], acc[mi][ni][3]);
                u64t F01 = fpoly2(D01);
                u64t F23 = fpoly2(D23);
                u64t W;
                MUL2(W, UU0, V);  FMA2(part2, W, F01, part2);
                MUL2(W, UU1, V);  FMA2(part2, W, F23, part2);
                u64t M01, M23;
                FMA2(M01, D01, NEG1, ONE);
                FMA2(M23, D23, NEG1, ONE);
                *(float2*)(p0 + n0) = *(float2*)&M01;
                *(float2*)(p1 + n0) = *(float2*)&M23;
            }
        }

        float plo, phi;
        asm("mov.b64 {%0, %1}, %2;" : "=f"(plo), "=f"(phi) : "l"(part2));
        float part = plo + phi;
        #pragma unroll
        for (int off = 16; off > 0; off >>= 1)
            part += __shfl_down_sync(0xffffffffu, part, off);
        if (lane == 0) atomicAdd(&g_sim[b], part);
    }
}

// ---------------- finalize --------------------------------------------------
__global__ void final_kernel(float* __restrict__ out) {
    int tid = threadIdx.x;
    float s = (tid < B_) ? g_sim[tid] : 0.f;
    if (tid < B_) out[MSIZE + tid] = s;
    float l = (tid < B_) ? (2.0f - 2.0f * s) : 0.f;
    #pragma unroll
    for (int off = 16; off > 0; off >>= 1)
        l += __shfl_down_sync(0xffffffffu, l, off);
    if (tid == 0) out[MSIZE + B_] = l * (1.0f / B_);
}

extern "C" void kernel_launch(void* const* d_in, const int* in_sizes, int n_in,
                              void* d_out, int out_size) {
    const float* X = (const float*)d_in[0];
    const float* Y = (const float*)d_in[1];
    float* out = (float*)d_out;

    cudaFuncSetAttribute(gemm_kernel, cudaFuncAttributeMaxDynamicSharedMemorySize, SMG_TOT);

    norm_kernel<false><<<dim3(18, B_), 256>>>(X);
    norm_kernel<true ><<<dim3(18, B_), 256>>>(Y);
    pass_kernel<<<dim3(18, B_), 256>>>(0);
    pass_kernel<<<dim3(18, B_), 256>>>(1);
    pass_kernel<<<dim3(18, B_), 256>>>(2);
    pass_kernel<<<dim3(18, B_), 256>>>(3);
    gemm_kernel<<<dim3(18, B_), 256, SMG_TOT>>>(out);
    final_kernel<<<1, 32>>>(out);
}